// round 9
// baseline (speedup 1.0000x reference)
#include <cuda_runtime.h>
#include <cuda_bf16.h>

#define NVSEG 29000
#define HWSZ  (1024 * 1024)
#define BATCH 16
#define BHW   (BATCH * HWSZ)

// __device__ globals are zero-initialized at module load.
// g_acc[v] = {sum_c0, sum_c1, sum_c2, count}. Invariant: zero at
// kernel_launch entry — replaced_kernel re-zeroes after consuming.
__device__ float4 g_acc[NVSEG];
__device__ float4 g_rep[NVSEG];

// Pass 1: 1 px/thread — minimum scattered-RED burst per thread, maximum
// eligible-warp interleave into the L1tex queue. One float4 RED per pixel.
__global__ __launch_bounds__(256) void accumulate_kernel(
    const float* __restrict__ img, const int* __restrict__ seg)
{
    const long p = (long)blockIdx.x * blockDim.x + threadIdx.x;  // 0 .. BHW
    const int  b = (int)(p >> 20);          // HW = 2^20
    const long rem = p & (HWSZ - 1);
    const float* base = img + (long)b * 3 * HWSZ + rem;

    const int   s  = seg[p];
    const float c0 = base[0 * HWSZ];
    const float c1 = base[1 * HWSZ];
    const float c2 = base[2 * HWSZ];

    atomicAdd(&g_acc[s], make_float4(c0, c1, c2, 1.0f));
}

// Pass 2: rep[v] = fV[v] - sums[v]/max(cnt,1); reset g_acc[v] = 0.
__global__ __launch_bounds__(512) void replaced_kernel(const float* __restrict__ fV) {
    int v = blockIdx.x * blockDim.x + threadIdx.x;
    if (v >= NVSEG) return;
    float4 a = g_acc[v];
    g_acc[v] = make_float4(0.f, 0.f, 0.f, 0.f);
    float inv = 1.0f / fmaxf(a.w, 1.0f);
    float4 r;
    r.x = fV[3 * v + 0] - a.x * inv;
    r.y = fV[3 * v + 1] - a.y * inv;
    r.z = fV[3 * v + 2] - a.z * inv;
    r.w = 0.f;
    g_rep[v] = r;
}

// Pass 3 (proven R3 form): 4 px/thread, gathers first, float4 stores.
__global__ __launch_bounds__(256) void output_kernel(
    const float* __restrict__ img, const int* __restrict__ seg,
    float* __restrict__ out)
{
    const long t = (long)blockIdx.x * blockDim.x + threadIdx.x;
    const long p = t << 2;
    const int  b = (int)(t >> 18);
    const long rem = p & (HWSZ - 1);
    const float* base = img + (long)b * 3 * HWSZ + rem;

    const int4 s = *(const int4*)(seg + p);

    const float4 r0 = g_rep[s.x];
    const float4 r1 = g_rep[s.y];
    const float4 r2 = g_rep[s.z];
    const float4 r3 = g_rep[s.w];

    const float4 c0 = *(const float4*)(base + 0 * HWSZ);
    const float4 c1 = *(const float4*)(base + 1 * HWSZ);
    const float4 c2 = *(const float4*)(base + 2 * HWSZ);

    float4 o0, o1, o2;
    o0.x = c0.x + r0.x;  o0.y = c1.x + r0.y;  o0.z = c2.x + r0.z;  o0.w = c0.y + r1.x;
    o1.x = c1.y + r1.y;  o1.y = c2.y + r1.z;  o1.z = c0.z + r2.x;  o1.w = c1.z + r2.y;
    o2.x = c2.z + r2.z;  o2.y = c0.w + r3.x;  o2.z = c1.w + r3.y;  o2.w = c2.w + r3.z;

    float4* dst = (float4*)(out + p * 3);   // 12t floats -> 16B aligned
    dst[0] = o0;
    dst[1] = o1;
    dst[2] = o2;
}

extern "C" void kernel_launch(void* const* d_in, const int* in_sizes, int n_in,
                              void* d_out, int out_size)
{
    const float* img = (const float*)d_in[0];
    const int*   seg = (const int*)d_in[1];
    const float* fV  = (const float*)d_in[2];
    float* out = (float*)d_out;

    const int nvBlocks = (NVSEG + 511) / 512;
    const int accBlocks = BHW / 256;         // 65536, 1 px/thread
    const int outBlocks = (BHW / 4) / 256;   // 16384

    accumulate_kernel<<<accBlocks, 256>>>(img, seg);
    replaced_kernel<<<nvBlocks, 512>>>(fV);
    output_kernel<<<outBlocks, 256>>>(img, seg, out);
}